// round 3
// baseline (speedup 1.0000x reference)
#include <cuda_runtime.h>
#include <cuda_fp16.h>
#include <cstdint>
#include <cstddef>

#define B_   128
#define S_   1024
#define IN_  256
#define H_   1024
#define G4_  4096
#define OUT_ 256
#define NC_  128   // CTAs in recurrence (1 per SM, all co-resident)
#define NJ_  8     // hidden units per CTA
#define NK_  20    // k-chunks per step: 4 (x, K=256) + 16 (h, K=1024)

// ---------------- scratch (static device globals; ~75 MB total) -----------
__device__ __half g_xT [(size_t)S_*B_*IN_];     // x transposed to [t][b][k] fp16 (64 MB)
__device__ __half g_WxT[(size_t)G4_*IN_];       // Wx transposed [n][k] fp16 (2 MB)
__device__ __half g_WhT[(size_t)G4_*H_];        // Wh transposed [n][k] fp16 (8 MB)
__device__ __half g_hbuf[2][(size_t)B_*H_];     // ping-pong h (0.5 MB)
__device__ unsigned g_cnt;                      // barrier arrivals (monotonic)
__device__ unsigned g_epoch;                    // barrier release epoch (monotonic)

// ---------------- small helpers -------------------------------------------
__device__ __forceinline__ void cp16(void* smem, const void* gmem){
    unsigned s = (unsigned)__cvta_generic_to_shared(smem);
    asm volatile("cp.async.cg.shared.global [%0], [%1], 16;\n" :: "r"(s), "l"(gmem));
}
__device__ __forceinline__ void cp_commit(){ asm volatile("cp.async.commit_group;\n"); }
template<int N> __device__ __forceinline__ void cp_wait(){ asm volatile("cp.async.wait_group %0;\n" :: "n"(N)); }

__device__ __forceinline__ void mma16816(float* c, uint32_t a0, uint32_t a1, uint32_t a2, uint32_t a3,
                                         uint32_t b0, uint32_t b1){
    asm volatile(
        "mma.sync.aligned.m16n8k16.row.col.f32.f16.f16.f32 "
        "{%0,%1,%2,%3}, {%4,%5,%6,%7}, {%8,%9}, {%0,%1,%2,%3};\n"
        : "+f"(c[0]), "+f"(c[1]), "+f"(c[2]), "+f"(c[3])
        : "r"(a0), "r"(a1), "r"(a2), "r"(a3), "r"(b0), "r"(b1));
}

__device__ __forceinline__ float sigm_(float x){ return 1.f / (1.f + __expf(-x)); }
__device__ __forceinline__ float tanh_(float x){ return 2.f / (1.f + __expf(-2.f*x)) - 1.f; }

// global barrier: monotonic epoch counting, safe across graph replays
__device__ __forceinline__ void gsync(){
    __syncthreads();
    if (threadIdx.x == 0){
        __threadfence();
        unsigned t = atomicAdd(&g_cnt, 1u) + 1u;
        unsigned target = (t + NC_ - 1u) / NC_;
        if (t == target * NC_){
            asm volatile("st.release.gpu.u32 [%0], %1;\n" :: "l"(&g_epoch), "r"(target) : "memory");
        } else {
            unsigned e;
            do { asm volatile("ld.acquire.gpu.u32 %0, [%1];\n" : "=r"(e) : "l"(&g_epoch) : "memory"); }
            while (e < target);
        }
    }
    __syncthreads();
}

// ---------------- phase 0: converts ---------------------------------------
// x[b][s][k] fp32 -> g_xT[(s*B + b)*IN + k] fp16
__global__ void conv_xT_kernel(const float* __restrict__ x){
    size_t n = (size_t)B_*S_*IN_;
    for (size_t i = (size_t)blockIdx.x*blockDim.x + threadIdx.x; i < n; i += (size_t)gridDim.x*blockDim.x){
        size_t k  = i % IN_;
        size_t bs = i / IN_;
        size_t s  = bs % S_;
        size_t b  = bs / S_;
        g_xT[((size_t)s*B_ + b)*IN_ + k] = __float2half(x[i]);
    }
}
__global__ void conv_w_kernel(const float* __restrict__ Wx, const float* __restrict__ Wh){
    size_t n1 = (size_t)G4_*IN_, n2 = (size_t)G4_*H_;
    for (size_t i = (size_t)blockIdx.x*blockDim.x + threadIdx.x; i < n1 + n2; i += (size_t)gridDim.x*blockDim.x){
        if (i < n1){
            int n = (int)(i / IN_), k = (int)(i % IN_);
            g_WxT[i] = __float2half(Wx[(size_t)k*G4_ + n]);
        } else {
            size_t j = i - n1;
            int n = (int)(j / H_), k = (int)(j % H_);
            g_WhT[j] = __float2half(Wh[(size_t)k*G4_ + n]);
        }
    }
}
__global__ void zero_h_kernel(){
    size_t n = (size_t)B_*H_;
    for (size_t i = (size_t)blockIdx.x*blockDim.x + threadIdx.x; i < n; i += (size_t)gridDim.x*blockDim.x)
        g_hbuf[0][i] = __float2half(0.f);
}

// ---------------- recurrence (persistent, 128 CTAs, fused x-projection) ---
// CTA owns j in [j0, j0+8): 32 gate columns. Wh slice (32x1024) + Wx slice
// (32x256) resident in smem for all 1024 steps. Per step the K loop runs 20
// chunks of 64: chunks 0-3 stream x_t (K=256), chunks 4-19 stream h (K=1024),
// all through one 3-deep cp.async pipeline into 128x32 fp32 mma accumulators.
// Gate activations and cell state c are register-local.
constexpr int LDW_ = H_  + 8;   // Wh slice row stride (halfs)
constexpr int LDX_ = IN_ + 8;   // Wx slice row stride (halfs)
constexpr int LDH_ = 72;        // A-chunk row stride (halfs)
constexpr int SMEM_REC = (32*LDW_ + 32*LDX_ + 3*128*LDH_) * 2; // 138,240 B

__device__ __forceinline__ void loadChunk(__half* hs, int buf, int kc, int t, const __half* hsrc){
    int tid = threadIdx.x;
    #pragma unroll
    for (int i = 0; i < 4; i++){
        int o = tid + i*256;
        int r = o >> 3, seg = o & 7;
        const __half* src = (kc < 4)
            ? g_xT + ((size_t)t*B_ + r)*IN_ + kc*64 + seg*8
            : hsrc + (size_t)r*H_ + (kc - 4)*64 + seg*8;
        cp16(&hs[(buf*128 + r)*LDH_ + seg*8], src);
    }
}

__global__ __launch_bounds__(256,1) void lstm_rec_kernel(const float* __restrict__ bias){
    extern __shared__ __align__(16) __half sh[];
    __half* Whs = sh;                           // [32][LDW_]
    __half* Wxs = sh + 32*LDW_;                 // [32][LDX_]
    __half* hs  = sh + 32*LDW_ + 32*LDX_;       // [3][128][LDH_]
    int tid = threadIdx.x, lane = tid & 31, w = tid >> 5;
    int gid = lane >> 2, ctid = lane & 3;
    int j0 = blockIdx.x * NJ_;
    int mrow = w * 16;

    // load Wh slice once: row r = g*8+jj  <-  WhT row (g*1024 + j0 + jj)
    for (int o = tid; o < 32*128; o += 256){
        int r = o >> 7, seg = o & 127;
        cp16(&Whs[r*LDW_ + seg*8], g_WhT + ((size_t)((r>>3)*H_ + j0 + (r&7)))*H_ + seg*8);
    }
    // load Wx slice once: row r = g*8+jj  <-  WxT row (g*1024 + j0 + jj), 256 halfs
    for (int o = tid; o < 32*32; o += 256){
        int r = o >> 5, seg = o & 31;
        cp16(&Wxs[r*LDX_ + seg*8], g_WxT + ((size_t)((r>>3)*H_ + j0 + (r&7)))*IN_ + seg*8);
    }
    cp_commit(); cp_wait<0>(); __syncthreads();

    // bias for this thread's gate columns (j0 + ctid*2, +1), all 4 gates
    float2 bf  = *(const float2*)&bias[0*H_ + j0 + ctid*2];
    float2 bi  = *(const float2*)&bias[1*H_ + j0 + ctid*2];
    float2 bg  = *(const float2*)&bias[2*H_ + j0 + ctid*2];
    float2 bo  = *(const float2*)&bias[3*H_ + j0 + ctid*2];

    float cst[4] = {0.f, 0.f, 0.f, 0.f};   // c state: [mi*2+ji]

    for (int t = 0; t < S_; t++){
        const __half* __restrict__ hsrc = g_hbuf[t & 1];
        __half* __restrict__ hdst = g_hbuf[(t + 1) & 1];

        float acc[4][4];
        #pragma unroll
        for (int i = 0; i < 4; i++){ acc[i][0]=0; acc[i][1]=0; acc[i][2]=0; acc[i][3]=0; }

        loadChunk(hs, 0, 0, t, hsrc); cp_commit();
        loadChunk(hs, 1, 1, t, hsrc); cp_commit();
        for (int kc = 0; kc < NK_; kc++){
            if (kc + 2 < NK_) loadChunk(hs, (kc+2)%3, kc+2, t, hsrc);
            cp_commit();
            cp_wait<2>(); __syncthreads();
            const __half* hb = hs + (kc % 3)*128*LDH_;
            const __half* Bb = (kc < 4) ? (Wxs + kc*64) : (Whs + (kc-4)*64);
            int ldb = (kc < 4) ? LDX_ : LDW_;
            #pragma unroll
            for (int kk = 0; kk < 64; kk += 16){
                uint32_t a0 = *(const uint32_t*)&hb[(mrow+gid  )*LDH_ + kk + ctid*2    ];
                uint32_t a1 = *(const uint32_t*)&hb[(mrow+gid+8)*LDH_ + kk + ctid*2    ];
                uint32_t a2 = *(const uint32_t*)&hb[(mrow+gid  )*LDH_ + kk + ctid*2 + 8];
                uint32_t a3 = *(const uint32_t*)&hb[(mrow+gid+8)*LDH_ + kk + ctid*2 + 8];
                #pragma unroll
                for (int nt = 0; nt < 4; nt++){
                    const __half* wr = Bb + (nt*8 + gid)*ldb + kk + ctid*2;
                    uint32_t b0 = *(const uint32_t*)wr;
                    uint32_t b1 = *(const uint32_t*)(wr + 8);
                    mma16816(acc[nt], a0, a1, a2, a3, b0, b1);
                }
            }
            __syncthreads();
        }

        // epilogue: + bias -> activations -> c,h update (register-local)
        #pragma unroll
        for (int mi = 0; mi < 2; mi++){
            int m = mrow + gid + mi*8;
            __half2 hv;
            #pragma unroll
            for (int ji = 0; ji < 2; ji++){
                int c = mi*2 + ji;
                float fg = sigm_(acc[0][c] + (ji ? bf.y : bf.x));
                float ig = sigm_(acc[1][c] + (ji ? bi.y : bi.x));
                float gg = tanh_(acc[2][c] + (ji ? bg.y : bg.x));
                float og = sigm_(acc[3][c] + (ji ? bo.y : bo.x));
                float cn = fg*cst[c] + ig*gg;
                cst[c] = cn;
                float hn = og * tanh_(cn);
                if (ji == 0) hv.x = __float2half(hn); else hv.y = __float2half(hn);
            }
            *(__half2*)&hdst[(size_t)m*H_ + j0 + ctid*2] = hv;
        }
        gsync();
    }
}

// ---------------- final FC: out = h_T @ Wfc + bfc (fp32) ------------------
__global__ __launch_bounds__(256) void fc_kernel(const float* __restrict__ Wfc,
                                                 const float* __restrict__ bfc,
                                                 float* __restrict__ out){
    __shared__ float hsm[H_];
    int b = blockIdx.x, o = threadIdx.x;
    const __half* hr = g_hbuf[0] + (size_t)b*H_;  // S even -> final h in buffer 0
    for (int k = o; k < H_; k += 256) hsm[k] = __half2float(hr[k]);
    __syncthreads();
    float s = bfc[o];
    #pragma unroll 8
    for (int k = 0; k < H_; k++) s = fmaf(hsm[k], Wfc[(size_t)k*OUT_ + o], s);
    out[(size_t)b*OUT_ + o] = s;
}

// ---------------- entry ----------------------------------------------------
extern "C" void kernel_launch(void* const* d_in, const int* in_sizes, int n_in,
                              void* d_out, int out_size){
    (void)in_sizes; (void)n_in; (void)out_size;
    const float* x   = (const float*)d_in[0];
    const float* Wx  = (const float*)d_in[1];
    const float* Wh  = (const float*)d_in[2];
    const float* b   = (const float*)d_in[3];
    const float* Wfc = (const float*)d_in[4];
    const float* bfc = (const float*)d_in[5];
    float* out = (float*)d_out;

    cudaFuncSetAttribute(lstm_rec_kernel, cudaFuncAttributeMaxDynamicSharedMemorySize, SMEM_REC);

    conv_xT_kernel<<<2048, 256>>>(x);
    conv_w_kernel<<<1024, 256>>>(Wx, Wh);
    zero_h_kernel<<<256, 256>>>();
    lstm_rec_kernel<<<NC_, 256, SMEM_REC>>>(b);
    fc_kernel<<<B_, 256>>>(Wfc, bfc, out);
}

// round 4
// speedup vs baseline: 1.3468x; 1.3468x over previous
#include <cuda_runtime.h>
#include <cuda_fp16.h>
#include <cstdint>
#include <cstddef>

#define B_   128
#define S_   1024
#define IN_  256
#define H_   1024
#define G4_  4096
#define OUT_ 256
#define NC_  128   // CTAs in recurrence (1 per SM, all co-resident)
#define NJ_  8     // hidden units per CTA
#define ND_  4     // per-warp pipeline depth

// ---------------- scratch (static device globals; ~75 MB total) -----------
__device__ __half g_xT [(size_t)S_*B_*IN_];     // x transposed to [t][b][k] fp16 (64 MB)
__device__ __half g_WxT[(size_t)G4_*IN_];       // Wx transposed [n][k] fp16 (2 MB)
__device__ __half g_WhT[(size_t)G4_*H_];        // Wh transposed [n][k] fp16 (8 MB)
__device__ __half g_hbuf[2][(size_t)B_*H_];     // ping-pong h (0.5 MB)
__device__ unsigned g_cnt;                      // barrier arrivals (monotonic)
__device__ unsigned g_epoch;                    // barrier release epoch (monotonic)

// ---------------- small helpers -------------------------------------------
__device__ __forceinline__ void cp16(void* smem, const void* gmem){
    unsigned s = (unsigned)__cvta_generic_to_shared(smem);
    asm volatile("cp.async.cg.shared.global [%0], [%1], 16;\n" :: "r"(s), "l"(gmem));
}
__device__ __forceinline__ void cp_commit(){ asm volatile("cp.async.commit_group;\n"); }
template<int N> __device__ __forceinline__ void cp_wait(){ asm volatile("cp.async.wait_group %0;\n" :: "n"(N)); }

__device__ __forceinline__ void mma16816(float* c, uint32_t a0, uint32_t a1, uint32_t a2, uint32_t a3,
                                         uint32_t b0, uint32_t b1){
    asm volatile(
        "mma.sync.aligned.m16n8k16.row.col.f32.f16.f16.f32 "
        "{%0,%1,%2,%3}, {%4,%5,%6,%7}, {%8,%9}, {%0,%1,%2,%3};\n"
        : "+f"(c[0]), "+f"(c[1]), "+f"(c[2]), "+f"(c[3])
        : "r"(a0), "r"(a1), "r"(a2), "r"(a3), "r"(b0), "r"(b1));
}

__device__ __forceinline__ float sigm_(float x){ return 1.f / (1.f + __expf(-x)); }
__device__ __forceinline__ float tanh_(float x){ return 2.f / (1.f + __expf(-2.f*x)) - 1.f; }

// ---------------- phase 0: converts ---------------------------------------
__global__ void conv_xT_kernel(const float* __restrict__ x){
    size_t n = (size_t)B_*S_*IN_;
    for (size_t i = (size_t)blockIdx.x*blockDim.x + threadIdx.x; i < n; i += (size_t)gridDim.x*blockDim.x){
        size_t k  = i % IN_;
        size_t bs = i / IN_;
        size_t s  = bs % S_;
        size_t b  = bs / S_;
        g_xT[((size_t)s*B_ + b)*IN_ + k] = __float2half(x[i]);
    }
}
__global__ void conv_w_kernel(const float* __restrict__ Wx, const float* __restrict__ Wh){
    size_t n1 = (size_t)G4_*IN_, n2 = (size_t)G4_*H_;
    for (size_t i = (size_t)blockIdx.x*blockDim.x + threadIdx.x; i < n1 + n2; i += (size_t)gridDim.x*blockDim.x){
        if (i < n1){
            int n = (int)(i / IN_), k = (int)(i % IN_);
            g_WxT[i] = __float2half(Wx[(size_t)k*G4_ + n]);
        } else {
            size_t j = i - n1;
            int n = (int)(j / H_), k = (int)(j % H_);
            g_WhT[j] = __float2half(Wh[(size_t)k*G4_ + n]);
        }
    }
}
__global__ void zero_h_kernel(){
    size_t n = (size_t)B_*H_;
    for (size_t i = (size_t)blockIdx.x*blockDim.x + threadIdx.x; i < n; i += (size_t)gridDim.x*blockDim.x)
        g_hbuf[0][i] = __float2half(0.f);
}

// ---------------- recurrence (persistent, 128 CTAs) ------------------------
// CTA owns j in [j0, j0+8): 32 gate columns. Warp w owns batch rows
// [w*16, w*16+16) exclusively -> per-warp private cp.async A pipeline, NO
// block syncs inside the K loop. Per step: 16 h-chunks (K=1024) through a
// 4-deep per-warp pipeline; the 4 x-chunks (K=256) for step t+1 are computed
// in the shadow of the global barrier. c-state and activations register-local.
constexpr int LDW_ = H_  + 8;    // Wh slice row stride (halfs)
constexpr int LDX_ = IN_ + 8;    // Wx slice row stride (halfs)
constexpr int LDH_ = 72;         // A-chunk row stride (halfs)
constexpr int WBUF_ = ND_*16*LDH_;  // per-warp A smem (halfs)
constexpr int SMEM_REC = (32*LDW_ + 32*LDX_ + 8*WBUF_) * 2; // 156,672 B

// per-warp: load 16 rows x 64 halfs of A from src(row stride 'stride') into buf
__device__ __forceinline__ void loadA(__half* ws, int buf, const __half* src, int stride){
    int lane = threadIdx.x & 31;
    #pragma unroll
    for (int i = 0; i < 4; i++){
        int o = lane + i*32;
        int r = o >> 3, seg = o & 7;
        cp16(&ws[(buf*16 + r)*LDH_ + seg*8], src + (size_t)r*stride + seg*8);
    }
}

__global__ __launch_bounds__(256,1) void lstm_rec_kernel(const float* __restrict__ bias){
    extern __shared__ __align__(16) __half sh[];
    __half* Whs = sh;                           // [32][LDW_]
    __half* Wxs = sh + 32*LDW_;                 // [32][LDX_]
    __half* ws  = sh + 32*LDW_ + 32*LDX_ + (threadIdx.x >> 5)*WBUF_; // per-warp A bufs
    int tid = threadIdx.x, lane = tid & 31, w = tid >> 5;
    int gid = lane >> 2, ctid = lane & 3;
    int j0 = blockIdx.x * NJ_;
    int mrow = w * 16;

    // load Wh slice once: row r = g*8+jj  <-  WhT row (g*1024 + j0 + jj)
    for (int o = tid; o < 32*128; o += 256){
        int r = o >> 7, seg = o & 127;
        cp16(&Whs[r*LDW_ + seg*8], g_WhT + ((size_t)((r>>3)*H_ + j0 + (r&7)))*H_ + seg*8);
    }
    for (int o = tid; o < 32*32; o += 256){
        int r = o >> 5, seg = o & 31;
        cp16(&Wxs[r*LDX_ + seg*8], g_WxT + ((size_t)((r>>3)*H_ + j0 + (r&7)))*IN_ + seg*8);
    }
    cp_commit(); cp_wait<0>(); __syncthreads();

    float2 bf  = *(const float2*)&bias[0*H_ + j0 + ctid*2];
    float2 bi  = *(const float2*)&bias[1*H_ + j0 + ctid*2];
    float2 bg  = *(const float2*)&bias[2*H_ + j0 + ctid*2];
    float2 bo  = *(const float2*)&bias[3*H_ + j0 + ctid*2];

    float cst[4] = {0.f, 0.f, 0.f, 0.f};
    float acc[4][4];
    unsigned tgt = 0;   // thread0's barrier wait target

    // compute chunk from buf b: A = ws rows, B = Bb (stride ldb) at k-offset
    auto mmaChunk = [&](int buf, const __half* Bb, int ldb, int kbase){
        #pragma unroll
        for (int kk = 0; kk < 64; kk += 16){
            const __half* hb = ws + buf*16*LDH_;
            uint32_t a0 = *(const uint32_t*)&hb[(gid  )*LDH_ + kk + ctid*2    ];
            uint32_t a1 = *(const uint32_t*)&hb[(gid+8)*LDH_ + kk + ctid*2    ];
            uint32_t a2 = *(const uint32_t*)&hb[(gid  )*LDH_ + kk + ctid*2 + 8];
            uint32_t a3 = *(const uint32_t*)&hb[(gid+8)*LDH_ + kk + ctid*2 + 8];
            #pragma unroll
            for (int nt = 0; nt < 4; nt++){
                const __half* wr = Bb + (nt*8 + gid)*ldb + kbase + kk + ctid*2;
                uint32_t b0 = *(const uint32_t*)wr;
                uint32_t b1 = *(const uint32_t*)(wr + 8);
                mma16816(acc[nt], a0, a1, a2, a3, b0, b1);
            }
        }
    };

    // x-part for step tt: zero acc, add x_tt @ Wx^T slice (4 chunks, K=256)
    auto xPart = [&](int tt){
        #pragma unroll
        for (int i = 0; i < 4; i++){ acc[i][0]=0; acc[i][1]=0; acc[i][2]=0; acc[i][3]=0; }
        const __half* xb = g_xT + ((size_t)tt*B_ + mrow)*IN_;
        #pragma unroll
        for (int kc = 0; kc < 4; kc++){ loadA(ws, kc, xb + kc*64, IN_); cp_commit(); }
        cp_wait<0>();
        #pragma unroll
        for (int kc = 0; kc < 4; kc++) mmaChunk(kc, Wxs, LDX_, kc*64);
    };

    xPart(0);   // t=0 input projection (h0 = 0, no h-part needed for ordering)

    for (int t = 0; t < S_; t++){
        // wait for h_t (all CTAs arrived step t-1)
        if (t > 0){
            if (tid == 0){
                unsigned e;
                do { asm volatile("ld.acquire.gpu.u32 %0, [%1];\n" : "=r"(e) : "l"(&g_epoch) : "memory"); }
                while (e < tgt);
            }
            __syncthreads();
        }

        const __half* __restrict__ hsrc = g_hbuf[t & 1] + (size_t)mrow*H_;
        __half* __restrict__ hdst = g_hbuf[(t + 1) & 1];

        // h-part: 16 chunks, per-warp 4-deep pipeline, no block syncs
        loadA(ws, 0, hsrc,       H_); cp_commit();
        loadA(ws, 1, hsrc +  64, H_); cp_commit();
        loadA(ws, 2, hsrc + 128, H_); cp_commit();
        for (int kc = 0; kc < 16; kc++){
            if (kc + 3 < 16) loadA(ws, (kc+3) & 3, hsrc + (kc+3)*64, H_);
            cp_commit();
            cp_wait<3>();
            mmaChunk(kc & 3, Whs, LDW_, kc*64);
        }

        // epilogue: + bias -> activations -> c,h update (register-local)
        #pragma unroll
        for (int mi = 0; mi < 2; mi++){
            int m = mrow + gid + mi*8;
            __half2 hv;
            #pragma unroll
            for (int ji = 0; ji < 2; ji++){
                int c = mi*2 + ji;
                float fg = sigm_(acc[0][c] + (ji ? bf.y : bf.x));
                float ig = sigm_(acc[1][c] + (ji ? bi.y : bi.x));
                float gg = tanh_(acc[2][c] + (ji ? bg.y : bg.x));
                float og = sigm_(acc[3][c] + (ji ? bo.y : bo.x));
                float cn = fg*cst[c] + ig*gg;
                cst[c] = cn;
                float hn = og * tanh_(cn);
                if (ji == 0) hv.x = __float2half(hn); else hv.y = __float2half(hn);
            }
            *(__half2*)&hdst[(size_t)m*H_ + j0 + ctid*2] = hv;
        }

        __syncthreads();                    // all h stores issued
        if (tid == 0){                      // arrive (release)
            __threadfence();
            unsigned a = atomicAdd(&g_cnt, 1u) + 1u;
            tgt = (a + NC_ - 1u) / NC_;
            if (a == tgt * NC_)
                asm volatile("st.release.gpu.u32 [%0], %1;\n" :: "l"(&g_epoch), "r"(tgt) : "memory");
        }

        // x-part for t+1 in the barrier shadow (independent of h)
        if (t + 1 < S_) xPart(t + 1);
    }
}

// ---------------- final FC: out = h_T @ Wfc + bfc (fp32) ------------------
__global__ __launch_bounds__(256) void fc_kernel(const float* __restrict__ Wfc,
                                                 const float* __restrict__ bfc,
                                                 float* __restrict__ out){
    __shared__ float hsm[H_];
    int b = blockIdx.x, o = threadIdx.x;
    const __half* hr = g_hbuf[0] + (size_t)b*H_;  // S even -> final h in buffer 0
    for (int k = o; k < H_; k += 256) hsm[k] = __half2float(hr[k]);
    __syncthreads();
    float s = bfc[o];
    #pragma unroll 8
    for (int k = 0; k < H_; k++) s = fmaf(hsm[k], Wfc[(size_t)k*OUT_ + o], s);
    out[(size_t)b*OUT_ + o] = s;
}

// ---------------- entry ----------------------------------------------------
extern "C" void kernel_launch(void* const* d_in, const int* in_sizes, int n_in,
                              void* d_out, int out_size){
    (void)in_sizes; (void)n_in; (void)out_size;
    const float* x   = (const float*)d_in[0];
    const float* Wx  = (const float*)d_in[1];
    const float* Wh  = (const float*)d_in[2];
    const float* b   = (const float*)d_in[3];
    const float* Wfc = (const float*)d_in[4];
    const float* bfc = (const float*)d_in[5];
    float* out = (float*)d_out;

    cudaFuncSetAttribute(lstm_rec_kernel, cudaFuncAttributeMaxDynamicSharedMemorySize, SMEM_REC);

    conv_xT_kernel<<<2048, 256>>>(x);
    conv_w_kernel<<<1024, 256>>>(Wx, Wh);
    zero_h_kernel<<<256, 256>>>();
    lstm_rec_kernel<<<NC_, 256, SMEM_REC>>>(b);
    fc_kernel<<<B_, 256>>>(Wfc, bfc, out);
}

// round 5
// speedup vs baseline: 1.5091x; 1.1205x over previous
#include <cuda_runtime.h>
#include <cuda_fp16.h>
#include <cstdint>
#include <cstddef>

#define B_   128
#define S_   1024
#define IN_  256
#define H_   1024
#define G4_  4096
#define OUT_ 256
#define NC_  128   // CTAs in recurrence (1 per SM, all co-resident)
#define NDEP 6     // per-warp bulk pipeline depth (stages)

// ---------------- scratch (static device globals) --------------------------
// Blocked+swizzled activations: chunk = 2048B = 16 rows x 64 cols fp16,
// row-major within chunk, bytes swizzled with o ^ ((o>>3)&0x70).
// g_x : [t][bblk(8)][kc(4)][2048B]      (64 MB)
// g_h : [buf][bblk(8)][kc(16)][2048B]   (2 x 256 KB)
__device__ __align__(128) __half g_x [(size_t)S_*B_*IN_];
__device__ __align__(128) __half g_WxT[(size_t)G4_*IN_];
__device__ __align__(128) __half g_WhT[(size_t)G4_*H_];
__device__ __align__(128) __half g_h[2][(size_t)B_*H_];
__device__ unsigned g_cnt;                      // barrier counter (reset by zero kernel)

__device__ __host__ __forceinline__ int swz(int o){ return o ^ ((o >> 3) & 0x70); }

// ---------------- small helpers -------------------------------------------
__device__ __forceinline__ void cp16(void* smem, const void* gmem){
    unsigned s = (unsigned)__cvta_generic_to_shared(smem);
    asm volatile("cp.async.cg.shared.global [%0], [%1], 16;\n" :: "r"(s), "l"(gmem));
}
__device__ __forceinline__ void cp_commit(){ asm volatile("cp.async.commit_group;\n"); }
template<int N> __device__ __forceinline__ void cp_wait(){ asm volatile("cp.async.wait_group %0;\n" :: "n"(N)); }

__device__ __forceinline__ void mma16816(float* c, uint32_t a0, uint32_t a1, uint32_t a2, uint32_t a3,
                                         uint32_t b0, uint32_t b1){
    asm volatile(
        "mma.sync.aligned.m16n8k16.row.col.f32.f16.f16.f32 "
        "{%0,%1,%2,%3}, {%4,%5,%6,%7}, {%8,%9}, {%0,%1,%2,%3};\n"
        : "+f"(c[0]), "+f"(c[1]), "+f"(c[2]), "+f"(c[3])
        : "r"(a0), "r"(a1), "r"(a2), "r"(a3), "r"(b0), "r"(b1));
}

__device__ __forceinline__ float sigm_(float x){ return 1.f / (1.f + __expf(-x)); }
__device__ __forceinline__ float tanh_(float x){ return 2.f / (1.f + __expf(-2.f*x)) - 1.f; }

__device__ __forceinline__ void mbar_init(uint32_t mbar, uint32_t cnt){
    asm volatile("mbarrier.init.shared.b64 [%0], %1;\n" :: "r"(mbar), "r"(cnt) : "memory");
}
__device__ __forceinline__ void mbar_expect_tx(uint32_t mbar, uint32_t tx){
    asm volatile("mbarrier.arrive.expect_tx.shared.b64 _, [%0], %1;\n" :: "r"(mbar), "r"(tx) : "memory");
}
__device__ __forceinline__ void bulk_g2s(uint32_t sdst, const void* gsrc, uint32_t bytes, uint32_t mbar){
    asm volatile("cp.async.bulk.shared::cluster.global.mbarrier::complete_tx::bytes [%0], [%1], %2, [%3];\n"
                 :: "r"(sdst), "l"(gsrc), "r"(bytes), "r"(mbar) : "memory");
}
__device__ __forceinline__ void mbar_wait(uint32_t mbar, uint32_t parity){
    asm volatile(
        "{\n\t.reg .pred P1;\n\t"
        "LAB_WAIT_%=:\n\t"
        "mbarrier.try_wait.parity.acquire.cta.shared::cta.b64 P1, [%0], %1;\n\t"
        "@P1 bra LAB_DONE_%=;\n\t"
        "bra LAB_WAIT_%=;\n\t"
        "LAB_DONE_%=:\n\t}"
        :: "r"(mbar), "r"(parity) : "memory");
}

// ---------------- phase 0: converts ---------------------------------------
// x[b][s][k] fp32 -> blocked/swizzled g_x
__global__ void conv_x_kernel(const float* __restrict__ x){
    size_t n = (size_t)B_*S_*IN_;
    char* base = (char*)g_x;
    for (size_t i = (size_t)blockIdx.x*blockDim.x + threadIdx.x; i < n; i += (size_t)gridDim.x*blockDim.x){
        int k  = (int)(i % IN_);
        size_t bs = i / IN_;
        int s  = (int)(bs % S_);
        int b  = (int)(bs / S_);
        size_t chunk = ((size_t)s*8 + (b >> 4))*4 + (k >> 6);
        int o = (b & 15)*128 + (k & 63)*2;
        *(__half*)(base + chunk*2048 + swz(o)) = __float2half(x[i]);
    }
}
__global__ void conv_w_kernel(const float* __restrict__ Wx, const float* __restrict__ Wh){
    size_t n1 = (size_t)G4_*IN_, n2 = (size_t)G4_*H_;
    for (size_t i = (size_t)blockIdx.x*blockDim.x + threadIdx.x; i < n1 + n2; i += (size_t)gridDim.x*blockDim.x){
        if (i < n1){
            int n = (int)(i / IN_), k = (int)(i % IN_);
            g_WxT[i] = __float2half(Wx[(size_t)k*G4_ + n]);
        } else {
            size_t j = i - n1;
            int n = (int)(j / H_), k = (int)(j % H_);
            g_WhT[j] = __float2half(Wh[(size_t)k*G4_ + n]);
        }
    }
}
__global__ void zero_h_kernel(){
    size_t n = (size_t)2*B_*H_;
    __half* p = (__half*)g_h;
    for (size_t i = (size_t)blockIdx.x*blockDim.x + threadIdx.x; i < n; i += (size_t)gridDim.x*blockDim.x)
        p[i] = __float2half(0.f);
    if (blockIdx.x == 0 && threadIdx.x == 0) g_cnt = 0u;   // reset barrier counter pre-launch
}

// ---------------- recurrence (persistent, 128 CTAs) ------------------------
// CTA owns 8 hidden units j0..j0+7 (32 gate cols). Warp w owns batch rows
// [w*16, w*16+16). Per step per warp: 16 h-chunks + 4 x-chunks, each ONE
// cp.async.bulk of 2KB through a 6-deep per-warp mbarrier ring. No block
// syncs in the K loop. Barrier: fire-and-forget red.add + poll absolute count.
constexpr int LDW_ = H_  + 8;    // Wh slice row stride (halfs)
constexpr int LDX_ = IN_ + 8;    // Wx slice row stride (halfs)
constexpr int WHS_BYTES = 32*LDW_*2;                 // 66048
constexpr int WXS_BYTES = 32*LDX_*2;                 // 16896
constexpr int ABUF_OFF  = WHS_BYTES + WXS_BYTES;     // 82944 (128-aligned)
constexpr int ABUF_BYTES= 8*NDEP*2048;               // 98304
constexpr int MBAR_OFF  = ABUF_OFF + ABUF_BYTES;     // 181248
constexpr int SMEM_REC  = MBAR_OFF + 8*NDEP*8;       // 181632 B

__global__ __launch_bounds__(256,1) void lstm_rec_kernel(const float* __restrict__ bias){
    extern __shared__ __align__(128) char sh[];
    __half* Whs = (__half*)sh;
    __half* Wxs = (__half*)(sh + WHS_BYTES);
    int tid = threadIdx.x, lane = tid & 31, w = tid >> 5;
    int gid = lane >> 2, ctid = lane & 3;
    int j0 = blockIdx.x * 8;
    int mrow = w * 16;

    char* Ab = sh + ABUF_OFF + w*NDEP*2048;                        // per-warp stages
    uint32_t Ab_s   = (uint32_t)__cvta_generic_to_shared(Ab);
    uint32_t mbar0  = (uint32_t)__cvta_generic_to_shared(sh + MBAR_OFF) + w*NDEP*8;

    // init all mbarriers (count=1 per use, completion via expect_tx)
    if (tid == 0){
        for (int i = 0; i < 8*NDEP; i++)
            mbar_init((uint32_t)__cvta_generic_to_shared(sh + MBAR_OFF) + i*8, 1);
        asm volatile("fence.proxy.async.shared::cta;\n" ::: "memory");
    }

    // resident weight slices (one-time cp.async)
    for (int o = tid; o < 32*128; o += 256){
        int r = o >> 7, seg = o & 127;
        cp16(&Whs[r*LDW_ + seg*8], g_WhT + ((size_t)((r>>3)*H_ + j0 + (r&7)))*H_ + seg*8);
    }
    for (int o = tid; o < 32*32; o += 256){
        int r = o >> 5, seg = o & 31;
        cp16(&Wxs[r*LDX_ + seg*8], g_WxT + ((size_t)((r>>3)*H_ + j0 + (r&7)))*IN_ + seg*8);
    }
    cp_commit(); cp_wait<0>(); __syncthreads();

    float2 bf = *(const float2*)&bias[0*H_ + j0 + ctid*2];
    float2 bi = *(const float2*)&bias[1*H_ + j0 + ctid*2];
    float2 bg = *(const float2*)&bias[2*H_ + j0 + ctid*2];
    float2 bo = *(const float2*)&bias[3*H_ + j0 + ctid*2];

    float cst[4] = {0.f, 0.f, 0.f, 0.f};
    float acc[4][4];

    int ist = 0;              // issue stage cursor
    int cstg = 0, cph = 0;    // consume stage cursor + parity

    auto issueChunk = [&](const char* gsrc){
        if (lane == 0){
            uint32_t mb = mbar0 + (uint32_t)ist*8;
            mbar_expect_tx(mb, 2048u);
            bulk_g2s(Ab_s + (uint32_t)ist*2048, gsrc, 2048u, mb);
        }
        ist = (ist + 1 == NDEP) ? 0 : ist + 1;
    };
    auto waitChunk = [&]() -> int {
        int s = cstg;
        mbar_wait(mbar0 + (uint32_t)s*8, (uint32_t)cph);
        if (++cstg == NDEP){ cstg = 0; cph ^= 1; }
        return s;
    };

    // compute one 64-wide K chunk from stage s against B slice (stride ldb)
    auto mmaChunk = [&](int s, const __half* Bb, int ldb, int kbase){
        const char* hb = Ab + s*2048;
        int co = (ctid*2)*2;
        int xr = gid << 4;
        #pragma unroll
        for (int kk = 0; kk < 64; kk += 16){
            int cb = co + kk*2;
            uint32_t a0 = *(const uint32_t*)(hb + (((gid  )*128 + cb     ) ^ xr));
            uint32_t a1 = *(const uint32_t*)(hb + (((gid+8)*128 + cb     ) ^ xr));
            uint32_t a2 = *(const uint32_t*)(hb + (((gid  )*128 + cb + 16) ^ xr));
            uint32_t a3 = *(const uint32_t*)(hb + (((gid+8)*128 + cb + 16) ^ xr));
            #pragma unroll
            for (int nt = 0; nt < 4; nt++){
                const __half* wr = Bb + (nt*8 + gid)*ldb + kbase + kk + ctid*2;
                uint32_t b0 = *(const uint32_t*)wr;
                uint32_t b1 = *(const uint32_t*)(wr + 8);
                mma16816(acc[nt], a0, a1, a2, a3, b0, b1);
            }
        }
    };

    // x-projection for step tt (4 chunks): zeroes acc, runs in barrier shadow
    auto xPart = [&](int tt){
        #pragma unroll
        for (int i = 0; i < 4; i++){ acc[i][0]=0; acc[i][1]=0; acc[i][2]=0; acc[i][3]=0; }
        const char* xb = (const char*)g_x + (((size_t)tt*8 + w)*4)*2048;
        #pragma unroll
        for (int kc = 0; kc < 4; kc++) issueChunk(xb + kc*2048);
        #pragma unroll
        for (int kc = 0; kc < 4; kc++){ int s = waitChunk(); mmaChunk(s, Wxs, LDX_, kc*64); }
    };

    __syncthreads();   // mbarrier init visible to all warps
    xPart(0);

    for (int t = 0; t < S_; t++){
        // wait for h_t: all CTAs arrived for step t-1 (absolute count t*NC_)
        if (t > 0){
            if (tid == 0){
                unsigned v;
                do { asm volatile("ld.acquire.gpu.global.u32 %0, [%1];\n" : "=r"(v) : "l"(&g_cnt) : "memory"); }
                while (v < (unsigned)t * NC_);
            }
            __syncthreads();
        }

        const char* hsrc = (const char*)g_h[t & 1] + (size_t)w*16*2048;
        // h-part: 16 chunks through the bulk ring, lookahead NDEP-1 = 5
        #pragma unroll
        for (int kc = 0; kc < 5; kc++) issueChunk(hsrc + kc*2048);
        for (int kc = 0; kc < 16; kc++){
            if (kc + 5 < 16) issueChunk(hsrc + (kc+5)*2048);
            int s = waitChunk();
            mmaChunk(s, Whs, LDW_, kc*64);
        }

        // epilogue: + bias -> activations -> c,h update (register-local)
        char* hdst = (char*)g_h[(t + 1) & 1] + ((size_t)(w*16 + (j0 >> 6)))*2048;
        int cbase = (j0 & 63)*2 + ctid*4;
        #pragma unroll
        for (int mi = 0; mi < 2; mi++){
            __half2 hv;
            #pragma unroll
            for (int ji = 0; ji < 2; ji++){
                int c = mi*2 + ji;
                float fg = sigm_(acc[0][c] + (ji ? bf.y : bf.x));
                float ig = sigm_(acc[1][c] + (ji ? bi.y : bi.x));
                float gg = tanh_(acc[2][c] + (ji ? bg.y : bg.x));
                float og = sigm_(acc[3][c] + (ji ? bo.y : bo.x));
                float cn = fg*cst[c] + ig*gg;
                cst[c] = cn;
                float hn = og * tanh_(cn);
                if (ji == 0) hv.x = __float2half(hn); else hv.y = __float2half(hn);
            }
            int r = gid + mi*8;
            int o = r*128 + cbase;
            *(uint32_t*)(hdst + (o ^ (gid << 4))) = *(uint32_t*)&hv;
        }

        __syncthreads();                    // all h stores issued by this CTA
        if (tid == 0){                      // fire-and-forget arrival
            __threadfence();
            asm volatile("red.release.gpu.global.add.u32 [%0], %1;\n" :: "l"(&g_cnt), "r"(1u) : "memory");
        }

        if (t + 1 < S_) xPart(t + 1);       // x-projection in the barrier shadow
    }
}

// ---------------- final FC: out = h_T @ Wfc + bfc (fp32) ------------------
__global__ __launch_bounds__(256) void fc_kernel(const float* __restrict__ Wfc,
                                                 const float* __restrict__ bfc,
                                                 float* __restrict__ out){
    __shared__ float hsm[H_];
    int b = blockIdx.x, o = threadIdx.x;
    const char* hb = (const char*)g_h[0];   // S even -> final h in buffer 0
    int row = b & 15, bblk = b >> 4;
    for (int k = o; k < H_; k += 256){
        size_t chunk = (size_t)bblk*16 + (k >> 6);
        int off = row*128 + (k & 63)*2;
        hsm[k] = __half2float(*(const __half*)(hb + chunk*2048 + swz(off)));
    }
    __syncthreads();
    float s = bfc[o];
    #pragma unroll 8
    for (int k = 0; k < H_; k++) s = fmaf(hsm[k], Wfc[(size_t)k*OUT_ + o], s);
    out[(size_t)b*OUT_ + o] = s;
}

// ---------------- entry ----------------------------------------------------
extern "C" void kernel_launch(void* const* d_in, const int* in_sizes, int n_in,
                              void* d_out, int out_size){
    (void)in_sizes; (void)n_in; (void)out_size;
    const float* x   = (const float*)d_in[0];
    const float* Wx  = (const float*)d_in[1];
    const float* Wh  = (const float*)d_in[2];
    const float* b   = (const float*)d_in[3];
    const float* Wfc = (const float*)d_in[4];
    const float* bfc = (const float*)d_in[5];
    float* out = (float*)d_out;

    cudaFuncSetAttribute(lstm_rec_kernel, cudaFuncAttributeMaxDynamicSharedMemorySize, SMEM_REC);

    conv_x_kernel<<<2048, 256>>>(x);
    conv_w_kernel<<<1024, 256>>>(Wx, Wh);
    zero_h_kernel<<<256, 256>>>();
    lstm_rec_kernel<<<NC_, 256, SMEM_REC>>>(b);
    fc_kernel<<<B_, 256>>>(Wfc, bfc, out);
}